// round 2
// baseline (speedup 1.0000x reference)
#include <cuda_runtime.h>
#include <cuda_bf16.h>
#include <cstdint>

// ---------------------------------------------------------------------------
// Problem shapes
// ---------------------------------------------------------------------------
#define B_SZ   1024
#define T_SZ   256
#define F_SZ   256
#define H_SZ   64
#define G4H    256          // 4*H
#define RB     8            // batch rows per block in recurrence kernel

// ---------------------------------------------------------------------------
// Scratch (device globals -- no allocations allowed)
// ---------------------------------------------------------------------------
__device__ float g_xw0[(size_t)T_SZ * B_SZ * G4H];   // 256 MB: layer0 input proj [T,B,4H]
__device__ float g_hout[(size_t)B_SZ * H_SZ];        // final layer1 hidden [B,64]
__device__ float g_mean[H_SZ];
__device__ float g_rstd[H_SZ];

__device__ __forceinline__ float sigf(float x) { return 1.f / (1.f + expf(-x)); }

// ---------------------------------------------------------------------------
// Kernel 1: input projection GEMM
//   g_xw0[t*1024+b][g] = sum_f x[b][t][f] * Wih0[g][f] + (bih0[g]+bhh0[g])
// 64x64 output tile, K-chunks of 32, 256 threads, 4x4 microtile.
// ---------------------------------------------------------------------------
__global__ __launch_bounds__(256) void input_gemm(
    const float* __restrict__ x,
    const float* __restrict__ Wih0,
    const float* __restrict__ bih0,
    const float* __restrict__ bhh0,
    float* __restrict__ xw0)
{
    __shared__ float As[64][33];
    __shared__ float Bs[64][33];

    const int tid = threadIdx.x;
    const int tx  = tid & 15;
    const int ty  = tid >> 4;
    const int m0  = blockIdx.x * 64;   // output row tile (m = t*1024 + b)
    const int n0  = blockIdx.y * 64;   // gate column tile

    float acc[4][4];
#pragma unroll
    for (int i = 0; i < 4; i++)
#pragma unroll
        for (int j = 0; j < 4; j++) acc[i][j] = 0.f;

    for (int k0 = 0; k0 < F_SZ; k0 += 32) {
        // load A tile: 64 rows x 32 k
#pragma unroll
        for (int i = tid; i < 64 * 32; i += 256) {
            int m  = i >> 5;
            int kk = i & 31;
            int mm = m0 + m;
            int t  = mm >> 10;          // / 1024
            int b  = mm & 1023;
            As[m][kk] = x[((size_t)b * T_SZ + t) * F_SZ + k0 + kk];
        }
        // load B tile: 64 gate-rows x 32 k
#pragma unroll
        for (int i = tid; i < 64 * 32; i += 256) {
            int n  = i >> 5;
            int kk = i & 31;
            Bs[n][kk] = Wih0[(size_t)(n0 + n) * F_SZ + k0 + kk];
        }
        __syncthreads();

#pragma unroll
        for (int k = 0; k < 32; k++) {
            float a[4], bv[4];
#pragma unroll
            for (int i = 0; i < 4; i++) a[i]  = As[ty * 4 + i][k];
#pragma unroll
            for (int j = 0; j < 4; j++) bv[j] = Bs[tx * 4 + j][k];
#pragma unroll
            for (int i = 0; i < 4; i++)
#pragma unroll
                for (int j = 0; j < 4; j++) acc[i][j] += a[i] * bv[j];
        }
        __syncthreads();
    }

#pragma unroll
    for (int j = 0; j < 4; j++) {
        int n = n0 + tx * 4 + j;
        float bias = bih0[n] + bhh0[n];
#pragma unroll
        for (int i = 0; i < 4; i++) {
            int m = m0 + ty * 4 + i;
            xw0[(size_t)m * G4H + n] = acc[i][j] + bias;
        }
    }
}

// ---------------------------------------------------------------------------
// Kernel 2: fused 2-layer LSTM recurrence.
// Each block: RB=8 batch rows, 256 threads (thread g owns gate output g).
// Weights Whh0ᵀ, Wih1ᵀ, Whh1ᵀ (j-major, [64][256]) + h/c state in SMEM.
// ---------------------------------------------------------------------------
#define SM_FLOATS (3*64*256 + 256 + 4*RB*64 + RB*256)

__global__ __launch_bounds__(256) void lstm_fused(
    const float* __restrict__ xw0,
    const float* __restrict__ Whh0,
    const float* __restrict__ Wih1,
    const float* __restrict__ Whh1,
    const float* __restrict__ bih1,
    const float* __restrict__ bhh1,
    float* __restrict__ hout)
{
    extern __shared__ float sm[];
    float* sW0 = sm;                    // Whh0ᵀ [64][256]
    float* sW1 = sW0 + 64 * 256;        // Wih1ᵀ
    float* sW2 = sW1 + 64 * 256;        // Whh1ᵀ
    float* sB1 = sW2 + 64 * 256;        // [256] bih1+bhh1
    float* h0  = sB1 + 256;             // [RB][64]
    float* c0  = h0 + RB * 64;
    float* h1  = c0 + RB * 64;
    float* c1  = h1 + RB * 64;
    float* zb  = c1 + RB * 64;          // [RB][256]

    const int tid = threadIdx.x;
    const int g   = tid;
    const int b0  = blockIdx.x * RB;

    // load weights transposed (one-time)
    for (int i = tid; i < 64 * 256; i += 256) {
        int gg = i >> 6, j = i & 63;
        sW0[j * 256 + gg] = Whh0[i];
        sW1[j * 256 + gg] = Wih1[i];
        sW2[j * 256 + gg] = Whh1[i];
    }
    sB1[tid] = bih1[tid] + bhh1[tid];
    for (int i = tid; i < RB * 64; i += 256) { h0[i] = 0.f; c0[i] = 0.f; h1[i] = 0.f; c1[i] = 0.f; }
    __syncthreads();

    for (int t = 0; t < T_SZ; t++) {
        // ---- layer 0: z0 = xw0[t] + Whh0 @ h0 ----
        float xv[RB];
        const float* xp = xw0 + ((size_t)t * B_SZ + b0) * G4H + g;
#pragma unroll
        for (int r = 0; r < RB; r++) xv[r] = xp[(size_t)r * G4H];

        float acc[RB];
#pragma unroll
        for (int r = 0; r < RB; r++) acc[r] = 0.f;
#pragma unroll
        for (int j4 = 0; j4 < 16; j4++) {
            float w0 = sW0[(4 * j4 + 0) * 256 + g];
            float w1 = sW0[(4 * j4 + 1) * 256 + g];
            float w2 = sW0[(4 * j4 + 2) * 256 + g];
            float w3 = sW0[(4 * j4 + 3) * 256 + g];
#pragma unroll
            for (int r = 0; r < RB; r++) {
                float4 hv = *(const float4*)&h0[r * 64 + 4 * j4];
                acc[r] += w0 * hv.x; acc[r] += w1 * hv.y;
                acc[r] += w2 * hv.z; acc[r] += w3 * hv.w;
            }
        }
#pragma unroll
        for (int r = 0; r < RB; r++) zb[r * 256 + g] = acc[r] + xv[r];
        __syncthreads();

        // ---- layer 0 pointwise gates ----
        for (int u = tid; u < RB * 64; u += 256) {
            int r = u >> 6, k = u & 63;
            const float* z = zb + r * 256;
            float zi = z[k], zf = z[64 + k], zg = z[128 + k], zo = z[192 + k];
            float cc = sigf(zf) * c0[u] + sigf(zi) * tanhf(zg);
            c0[u] = cc;
            h0[u] = sigf(zo) * tanhf(cc);
        }
        __syncthreads();

        // ---- layer 1: z1 = bias1 + Wih1 @ h0_new + Whh1 @ h1 ----
#pragma unroll
        for (int r = 0; r < RB; r++) acc[r] = sB1[g];
#pragma unroll
        for (int j4 = 0; j4 < 16; j4++) {
            float a0 = sW1[(4 * j4 + 0) * 256 + g];
            float a1 = sW1[(4 * j4 + 1) * 256 + g];
            float a2 = sW1[(4 * j4 + 2) * 256 + g];
            float a3 = sW1[(4 * j4 + 3) * 256 + g];
            float b0w = sW2[(4 * j4 + 0) * 256 + g];
            float b1w = sW2[(4 * j4 + 1) * 256 + g];
            float b2w = sW2[(4 * j4 + 2) * 256 + g];
            float b3w = sW2[(4 * j4 + 3) * 256 + g];
#pragma unroll
            for (int r = 0; r < RB; r++) {
                float4 hv = *(const float4*)&h0[r * 64 + 4 * j4];
                float4 gv = *(const float4*)&h1[r * 64 + 4 * j4];
                acc[r] += a0 * hv.x; acc[r] += a1 * hv.y;
                acc[r] += a2 * hv.z; acc[r] += a3 * hv.w;
                acc[r] += b0w * gv.x; acc[r] += b1w * gv.y;
                acc[r] += b2w * gv.z; acc[r] += b3w * gv.w;
            }
        }
#pragma unroll
        for (int r = 0; r < RB; r++) zb[r * 256 + g] = acc[r];
        __syncthreads();

        // ---- layer 1 pointwise gates ----
        for (int u = tid; u < RB * 64; u += 256) {
            int r = u >> 6, k = u & 63;
            const float* z = zb + r * 256;
            float zi = z[k], zf = z[64 + k], zg = z[128 + k], zo = z[192 + k];
            float cc = sigf(zf) * c1[u] + sigf(zi) * tanhf(zg);
            c1[u] = cc;
            h1[u] = sigf(zo) * tanhf(cc);
        }
        __syncthreads();
    }

    // final hidden of layer 1
    for (int u = tid; u < RB * 64; u += 256)
        hout[(size_t)b0 * 64 + u] = h1[u];
}

// ---------------------------------------------------------------------------
// Kernel 3: batchnorm statistics (one block per channel)
// ---------------------------------------------------------------------------
__global__ __launch_bounds__(256) void bn_stats(
    const float* __restrict__ h, float* __restrict__ mean, float* __restrict__ rstd)
{
    const int k = blockIdx.x;
    __shared__ float s1[256], s2[256];
    float a = 0.f, b = 0.f;
    for (int i = threadIdx.x; i < B_SZ; i += 256) {
        float v = h[(size_t)i * 64 + k];
        a += v; b += v * v;
    }
    s1[threadIdx.x] = a; s2[threadIdx.x] = b;
    __syncthreads();
    for (int s = 128; s > 0; s >>= 1) {
        if (threadIdx.x < s) { s1[threadIdx.x] += s1[threadIdx.x + s]; s2[threadIdx.x] += s2[threadIdx.x + s]; }
        __syncthreads();
    }
    if (threadIdx.x == 0) {
        float m = s1[0] / (float)B_SZ;
        float var = s2[0] / (float)B_SZ - m * m;
        mean[k] = m;
        rstd[k] = rsqrtf(var + 1e-5f);
    }
}

// ---------------------------------------------------------------------------
// Kernel 4: BN apply + MLP trunk + 3 heads. 32 rows per block.
// out layout: [0,3072) mc [B,3]; [3072,5120) co [B,2]; [5120,7168) ip [B,2]
// ---------------------------------------------------------------------------
__global__ __launch_bounds__(256) void mlp_head(
    const float* __restrict__ hbuf,
    const float* __restrict__ mean, const float* __restrict__ rstd,
    const float* __restrict__ gamma, const float* __restrict__ beta,
    const float* __restrict__ W1, const float* __restrict__ b1,
    const float* __restrict__ W2, const float* __restrict__ b2,
    const float* __restrict__ Wmc, const float* __restrict__ bmc,
    const float* __restrict__ Wco, const float* __restrict__ bco,
    const float* __restrict__ Wip, const float* __restrict__ bip,
    float* __restrict__ out)
{
    __shared__ float sH[32][64];
    __shared__ float sY1[32][64];
    __shared__ float sY2[32][32];
    __shared__ float sW1[64 * 64];
    __shared__ float sW2[32 * 64];
    __shared__ float sWh[7 * 32];
    __shared__ float sB1[64], sB2[32], sBh[7];

    const int tid = threadIdx.x;
    const int r0  = blockIdx.x * 32;

    for (int i = tid; i < 64 * 64; i += 256) sW1[i] = W1[i];
    for (int i = tid; i < 32 * 64; i += 256) sW2[i] = W2[i];
    for (int i = tid; i < 7 * 32; i += 256)
        sWh[i] = (i < 96) ? Wmc[i] : (i < 160 ? Wco[i - 96] : Wip[i - 160]);
    if (tid < 64) sB1[tid] = b1[tid];
    if (tid < 32) sB2[tid] = b2[tid];
    if (tid < 7)  sBh[tid] = (tid < 3) ? bmc[tid] : (tid < 5 ? bco[tid - 3] : bip[tid - 5]);

    for (int i = tid; i < 32 * 64; i += 256) {
        int r = i >> 6, k = i & 63;
        float v = hbuf[(size_t)(r0 + r) * 64 + k];
        sH[r][k] = (v - mean[k]) * rstd[k] * gamma[k] + beta[k];
    }
    __syncthreads();

    for (int i = tid; i < 32 * 64; i += 256) {
        int r = i >> 6, o = i & 63;
        float a = sB1[o];
#pragma unroll
        for (int k = 0; k < 64; k++) a += sW1[o * 64 + k] * sH[r][k];
        sY1[r][o] = fmaxf(a, 0.f);
    }
    __syncthreads();

    for (int i = tid; i < 32 * 32; i += 256) {
        int r = i >> 5, o = i & 31;
        float a = sB2[o];
#pragma unroll
        for (int k = 0; k < 64; k++) a += sW2[o * 64 + k] * sY1[r][k];
        sY2[r][o] = fmaxf(a, 0.f);
    }
    __syncthreads();

    for (int i = tid; i < 32 * 7; i += 256) {
        int r = i / 7, o = i % 7;
        float a = sBh[o];
#pragma unroll
        for (int k = 0; k < 32; k++) a += sWh[o * 32 + k] * sY2[r][k];
        int row = r0 + r;
        if (o < 3)       out[(size_t)row * 3 + o] = a;
        else if (o < 5)  out[3072 + (size_t)row * 2 + (o - 3)] = a;
        else             out[5120 + (size_t)row * 2 + (o - 5)] = a;
    }
}

// ---------------------------------------------------------------------------
// Launch
// ---------------------------------------------------------------------------
extern "C" void kernel_launch(void* const* d_in, const int* in_sizes, int n_in,
                              void* d_out, int out_size)
{
    const float* x      = (const float*)d_in[0];
    const float* Wih0   = (const float*)d_in[1];
    const float* Whh0   = (const float*)d_in[2];
    const float* bih0   = (const float*)d_in[3];
    const float* bhh0   = (const float*)d_in[4];
    const float* Wih1   = (const float*)d_in[5];
    const float* Whh1   = (const float*)d_in[6];
    const float* bih1   = (const float*)d_in[7];
    const float* bhh1   = (const float*)d_in[8];
    const float* gamma  = (const float*)d_in[9];
    const float* beta   = (const float*)d_in[10];
    const float* W_fc1  = (const float*)d_in[11];
    const float* b_fc1  = (const float*)d_in[12];
    const float* W_fc2  = (const float*)d_in[13];
    const float* b_fc2  = (const float*)d_in[14];
    const float* W_mc   = (const float*)d_in[15];
    const float* b_mc   = (const float*)d_in[16];
    const float* W_co   = (const float*)d_in[17];
    const float* b_co   = (const float*)d_in[18];
    const float* W_ip   = (const float*)d_in[19];
    const float* b_ip   = (const float*)d_in[20];
    float* out = (float*)d_out;

    float* xw0;   cudaGetSymbolAddress((void**)&xw0,  g_xw0);
    float* hout;  cudaGetSymbolAddress((void**)&hout, g_hout);
    float* mean;  cudaGetSymbolAddress((void**)&mean, g_mean);
    float* rstd;  cudaGetSymbolAddress((void**)&rstd, g_rstd);

    // 1. input projection GEMM: [T*B, 256] x [256, 256]
    {
        dim3 grid((T_SZ * B_SZ) / 64, G4H / 64);
        input_gemm<<<grid, 256>>>(x, Wih0, bih0, bhh0, xw0);
    }

    // 2. fused 2-layer recurrence
    {
        size_t smem = (size_t)SM_FLOATS * sizeof(float);
        cudaFuncSetAttribute(lstm_fused, cudaFuncAttributeMaxDynamicSharedMemorySize, (int)smem);
        lstm_fused<<<B_SZ / RB, 256, smem>>>(xw0, Whh0, Wih1, Whh1, bih1, bhh1, hout);
    }

    // 3. batchnorm statistics
    bn_stats<<<H_SZ, 256>>>(hout, mean, rstd);

    // 4. BN apply + MLP + heads
    mlp_head<<<B_SZ / 32, 256>>>(hout, mean, rstd, gamma, beta,
                                 W_fc1, b_fc1, W_fc2, b_fc2,
                                 W_mc, b_mc, W_co, b_co, W_ip, b_ip, out);
}

// round 5
// speedup vs baseline: 1.3513x; 1.3513x over previous
#include <cuda_runtime.h>
#include <cuda_bf16.h>
#include <cstdint>

typedef unsigned long long u64;

#define B_SZ   1024
#define T_SZ   256
#define F_SZ   256
#define H_SZ   64
#define G4H    256
#define RB     8

// ---------------------------------------------------------------------------
// Scratch (device globals)
// ---------------------------------------------------------------------------
__device__ float g_xw0[(size_t)T_SZ * B_SZ * G4H];   // [T,B,4H]
__device__ float g_hout[(size_t)B_SZ * H_SZ];
__device__ float g_mean[H_SZ];
__device__ float g_rstd[H_SZ];

// ---------------------------------------------------------------------------
// f32x2 packed helpers (Blackwell FFMA2 via PTX)
// ---------------------------------------------------------------------------
__device__ __forceinline__ u64 ffma2(u64 a, u64 b, u64 c) {
    u64 d;
    asm("fma.rn.f32x2 %0, %1, %2, %3;" : "=l"(d) : "l"(a), "l"(b), "l"(c));
    return d;
}
__device__ __forceinline__ float hadd2(u64 a) {
    float lo, hi;
    asm("mov.b64 {%0, %1}, %2;" : "=f"(lo), "=f"(hi) : "l"(a));
    return lo + hi;
}

__device__ __forceinline__ float sigf(float x) {
    return __fdividef(1.f, 1.f + __expf(-x));
}
__device__ __forceinline__ float tanhfast(float x) {
    // tanh(x) = 2*sigmoid(2x) - 1  (~1e-7 rel err with __expf)
    return 2.f * __fdividef(1.f, 1.f + __expf(-2.f * x)) - 1.f;
}

// ---------------------------------------------------------------------------
// Kernel 1: input projection GEMM  (f32x2 packed over k-pairs)
//   xw0[t*1024+b][g] = sum_f x[b][t][f]*Wih0[g][f] + bih0[g]+bhh0[g]
// Tile 128(m) x 64(n), k-chunk 32, 256 threads, micro 8m x 4n.
// ---------------------------------------------------------------------------
__global__ __launch_bounds__(256) void input_gemm(
    const float* __restrict__ x,
    const float* __restrict__ Wih0,
    const float* __restrict__ bih0,
    const float* __restrict__ bhh0,
    float* __restrict__ xw0)
{
    __shared__ float As[128][36];   // k contiguous
    __shared__ float Bs[64][36];
    __shared__ float sbias[64];

    const int tid = threadIdx.x;
    const int tx  = tid & 15;      // n dir
    const int ty  = tid >> 4;      // m dir
    const int m0  = blockIdx.x * 128;
    const int n0  = blockIdx.y * 64;

    if (tid < 64) sbias[tid] = bih0[n0 + tid] + bhh0[n0 + tid];

    u64 acc[8][4];
#pragma unroll
    for (int i = 0; i < 8; i++)
#pragma unroll
        for (int j = 0; j < 4; j++) acc[i][j] = 0ull;

    // all 128 rows of this block share one t (128 divides 1024)
    const int tt = m0 >> 10;

    for (int k0 = 0; k0 < F_SZ; k0 += 32) {
        // load A: 128 rows x 32 floats; 2 threads/row, 16 floats each
        {
            int row = tid >> 1, half = tid & 1;
            int b   = (m0 + row) & 1023;
            const float4* src = (const float4*)(x + ((size_t)b * T_SZ + tt) * F_SZ + k0 + half * 16);
            float4* dst = (float4*)&As[row][half * 16];
#pragma unroll
            for (int q = 0; q < 4; q++) dst[q] = src[q];
        }
        // load B: 64 rows x 32 floats; 4 threads/row, 8 floats each
        {
            int row = tid >> 2, q = tid & 3;
            const float4* src = (const float4*)(Wih0 + (size_t)(n0 + row) * F_SZ + k0 + q * 8);
            float4* dst = (float4*)&Bs[row][q * 8];
            dst[0] = src[0];
            dst[1] = src[1];
        }
        __syncthreads();

#pragma unroll
        for (int kk = 0; kk < 16; kk++) {
            u64 a[8], bb[4];
#pragma unroll
            for (int mi = 0; mi < 8; mi++)
                a[mi] = *(const u64*)&As[ty + mi * 16][2 * kk];
#pragma unroll
            for (int ni = 0; ni < 4; ni++)
                bb[ni] = *(const u64*)&Bs[tx + ni * 16][2 * kk];
#pragma unroll
            for (int mi = 0; mi < 8; mi++)
#pragma unroll
                for (int ni = 0; ni < 4; ni++)
                    acc[mi][ni] = ffma2(a[mi], bb[ni], acc[mi][ni]);
        }
        __syncthreads();
    }

#pragma unroll
    for (int mi = 0; mi < 8; mi++) {
        int m = m0 + ty + mi * 16;
#pragma unroll
        for (int ni = 0; ni < 4; ni++) {
            int nl = tx + ni * 16;
            xw0[(size_t)m * G4H + n0 + nl] = hadd2(acc[mi][ni]) + sbias[nl];
        }
    }
}

// ---------------------------------------------------------------------------
// Kernel 2: fused 2-layer LSTM recurrence (f32x2 over j-pairs).
// 128 threads = 64 k x 2 groups; each thread owns 4 batch rows and all 4
// gates for its k. Weight smem redundancy = 2 (vs 4 before): crossbar
// ~3100 cyc/step balances FFMA2 ~3072 cyc/step.
// Weights j-pair-interleaved: sw[((j>>1)*256+g)*2 + (j&1)] = W[g][j].
// c-state in registers; h double-buffered in SMEM -> 2 barriers/step.
// ---------------------------------------------------------------------------
#define LSTM_SMEM_FLOATS (3*16384 + 2*512 + 2*512)

__global__ __launch_bounds__(128) void lstm_fused(
    const float* __restrict__ xw0,
    const float* __restrict__ Whh0,
    const float* __restrict__ Wih1,
    const float* __restrict__ Whh1,
    const float* __restrict__ bih1,
    const float* __restrict__ bhh1,
    float* __restrict__ hout)
{
    extern __shared__ float sm[];
    float* sw0   = sm;                 // 16384
    float* sw1   = sm + 16384;
    float* sw2   = sm + 32768;
    float* h0buf = sm + 49152;         // [2][512]
    float* h1buf = sm + 49152 + 1024;  // [2][512]

    const int tid   = threadIdx.x;
    const int k     = tid & 63;
    const int grp   = tid >> 6;        // 0 or 1
    const int rbase = grp * 4;         // rows rbase..rbase+3
    const int b0    = blockIdx.x * RB;

    // one-time weight transform to j-pair-interleaved layout
    for (int i = tid; i < 16384; i += 128) {
        int g = i >> 6, j = i & 63;
        int d = ((j >> 1) * 256 + g) * 2 + (j & 1);
        sw0[d] = Whh0[i];
        sw1[d] = Wih1[i];
        sw2[d] = Whh1[i];
    }
    for (int i = tid; i < 1024; i += 128) { h0buf[i] = 0.f; h1buf[i] = 0.f; }

    float bz[4];
#pragma unroll
    for (int gi = 0; gi < 4; gi++) bz[gi] = bih1[gi * 64 + k] + bhh1[gi * 64 + k];

    const float* xp[4];
#pragma unroll
    for (int rr = 0; rr < 4; rr++)
        xp[rr] = xw0 + (size_t)(b0 + rbase + rr) * G4H + k;

    float xv[4][4];                    // [gate][row]
#pragma unroll
    for (int gi = 0; gi < 4; gi++)
#pragma unroll
        for (int rr = 0; rr < 4; rr++) xv[gi][rr] = xp[rr][gi * 64];

    float c0[4] = {0.f, 0.f, 0.f, 0.f};
    float c1[4] = {0.f, 0.f, 0.f, 0.f};
    float h1v[4] = {0.f, 0.f, 0.f, 0.f};

    __syncthreads();

    for (int t = 0; t < T_SZ; t++) {
        const float* h0r = h0buf + (t & 1) * 512;
        float*       h0w = h0buf + ((t + 1) & 1) * 512;
        const float* h1r = h1buf + (t & 1) * 512;
        float*       h1w = h1buf + ((t + 1) & 1) * 512;

        // ---- layer 0 matvec: Whh0 @ h0  (4 gates x 4 rows per thread) ----
        u64 acc[4][4];
#pragma unroll
        for (int gi = 0; gi < 4; gi++)
#pragma unroll
            for (int rr = 0; rr < 4; rr++) acc[gi][rr] = 0ull;

#pragma unroll 8
        for (int jj = 0; jj < 32; jj++) {
            const float* wrow = sw0 + jj * 512 + k * 2;
            u64 w[4];
            w[0] = *(const u64*)(wrow);
            w[1] = *(const u64*)(wrow + 128);
            w[2] = *(const u64*)(wrow + 256);
            w[3] = *(const u64*)(wrow + 384);
            u64 hv[4];
#pragma unroll
            for (int rr = 0; rr < 4; rr++)
                hv[rr] = *(const u64*)(h0r + (rbase + rr) * 64 + jj * 2);
#pragma unroll
            for (int gi = 0; gi < 4; gi++)
#pragma unroll
                for (int rr = 0; rr < 4; rr++)
                    acc[gi][rr] = ffma2(w[gi], hv[rr], acc[gi][rr]);
        }

        // ---- layer 0 gates (in-thread, c in regs) ----
#pragma unroll
        for (int rr = 0; rr < 4; rr++) {
            float zi = hadd2(acc[0][rr]) + xv[0][rr];
            float zf = hadd2(acc[1][rr]) + xv[1][rr];
            float zg = hadd2(acc[2][rr]) + xv[2][rr];
            float zo = hadd2(acc[3][rr]) + xv[3][rr];
            c0[rr] = sigf(zf) * c0[rr] + sigf(zi) * tanhfast(zg);
            h0w[(rbase + rr) * 64 + k] = sigf(zo) * tanhfast(c0[rr]);
        }

        // prefetch next timestep's x-projection (covers DRAM/L2 latency)
        if (t < T_SZ - 1) {
            size_t off = (size_t)(t + 1) * ((size_t)B_SZ * G4H);
#pragma unroll
            for (int gi = 0; gi < 4; gi++)
#pragma unroll
                for (int rr = 0; rr < 4; rr++)
                    xv[gi][rr] = xp[rr][off + gi * 64];
        }
        __syncthreads();   // h0(new) visible to all

        // ---- layer 1 matvec: Wih1 @ h0_new + Whh1 @ h1_old ----
#pragma unroll
        for (int gi = 0; gi < 4; gi++)
#pragma unroll
            for (int rr = 0; rr < 4; rr++) acc[gi][rr] = 0ull;

#pragma unroll 4
        for (int jj = 0; jj < 32; jj++) {
            const float* arow = sw1 + jj * 512 + k * 2;
            const float* brow = sw2 + jj * 512 + k * 2;
            u64 wa[4], wb[4];
            wa[0] = *(const u64*)(arow);
            wa[1] = *(const u64*)(arow + 128);
            wa[2] = *(const u64*)(arow + 256);
            wa[3] = *(const u64*)(arow + 384);
            wb[0] = *(const u64*)(brow);
            wb[1] = *(const u64*)(brow + 128);
            wb[2] = *(const u64*)(brow + 256);
            wb[3] = *(const u64*)(brow + 384);
            u64 h0v[4], h1vv[4];
#pragma unroll
            for (int rr = 0; rr < 4; rr++) {
                h0v[rr]  = *(const u64*)(h0w + (rbase + rr) * 64 + jj * 2);
                h1vv[rr] = *(const u64*)(h1r + (rbase + rr) * 64 + jj * 2);
            }
#pragma unroll
            for (int gi = 0; gi < 4; gi++)
#pragma unroll
                for (int rr = 0; rr < 4; rr++) {
                    acc[gi][rr] = ffma2(wa[gi], h0v[rr], acc[gi][rr]);
                    acc[gi][rr] = ffma2(wb[gi], h1vv[rr], acc[gi][rr]);
                }
        }

        // ---- layer 1 gates ----
#pragma unroll
        for (int rr = 0; rr < 4; rr++) {
            float zi = hadd2(acc[0][rr]) + bz[0];
            float zf = hadd2(acc[1][rr]) + bz[1];
            float zg = hadd2(acc[2][rr]) + bz[2];
            float zo = hadd2(acc[3][rr]) + bz[3];
            c1[rr] = sigf(zf) * c1[rr] + sigf(zi) * tanhfast(zg);
            h1v[rr] = sigf(zo) * tanhfast(c1[rr]);
            h1w[(rbase + rr) * 64 + k] = h1v[rr];
        }
        __syncthreads();   // h1(new) visible for next step
    }

#pragma unroll
    for (int rr = 0; rr < 4; rr++)
        hout[(size_t)(b0 + rbase + rr) * H_SZ + k] = h1v[rr];
}

// ---------------------------------------------------------------------------
// Kernel 3: batchnorm statistics
// ---------------------------------------------------------------------------
__global__ __launch_bounds__(256) void bn_stats(
    const float* __restrict__ h, float* __restrict__ mean, float* __restrict__ rstd)
{
    const int k = blockIdx.x;
    __shared__ float s1[256], s2[256];
    float a = 0.f, b = 0.f;
    for (int i = threadIdx.x; i < B_SZ; i += 256) {
        float v = h[(size_t)i * H_SZ + k];
        a += v; b += v * v;
    }
    s1[threadIdx.x] = a; s2[threadIdx.x] = b;
    __syncthreads();
    for (int s = 128; s > 0; s >>= 1) {
        if (threadIdx.x < s) { s1[threadIdx.x] += s1[threadIdx.x + s]; s2[threadIdx.x] += s2[threadIdx.x + s]; }
        __syncthreads();
    }
    if (threadIdx.x == 0) {
        float m = s1[0] / (float)B_SZ;
        float var = s2[0] / (float)B_SZ - m * m;
        mean[k] = m;
        rstd[k] = rsqrtf(var + 1e-5f);
    }
}

// ---------------------------------------------------------------------------
// Kernel 4: BN apply + MLP trunk + 3 heads
// out layout: [0,3072) mc [B,3]; [3072,5120) co [B,2]; [5120,7168) ip [B,2]
// ---------------------------------------------------------------------------
__global__ __launch_bounds__(256) void mlp_head(
    const float* __restrict__ hbuf,
    const float* __restrict__ mean, const float* __restrict__ rstd,
    const float* __restrict__ gamma, const float* __restrict__ beta,
    const float* __restrict__ W1, const float* __restrict__ b1,
    const float* __restrict__ W2, const float* __restrict__ b2,
    const float* __restrict__ Wmc, const float* __restrict__ bmc,
    const float* __restrict__ Wco, const float* __restrict__ bco,
    const float* __restrict__ Wip, const float* __restrict__ bip,
    float* __restrict__ out)
{
    __shared__ float sH[32][64];
    __shared__ float sY1[32][64];
    __shared__ float sY2[32][32];
    __shared__ float sW1[64 * 64];
    __shared__ float sW2[32 * 64];
    __shared__ float sWh[7 * 32];
    __shared__ float sB1[64], sB2[32], sBh[7];

    const int tid = threadIdx.x;
    const int r0  = blockIdx.x * 32;

    for (int i = tid; i < 64 * 64; i += 256) sW1[i] = W1[i];
    for (int i = tid; i < 32 * 64; i += 256) sW2[i] = W2[i];
    for (int i = tid; i < 7 * 32; i += 256)
        sWh[i] = (i < 96) ? Wmc[i] : (i < 160 ? Wco[i - 96] : Wip[i - 160]);
    if (tid < 64) sB1[tid] = b1[tid];
    if (tid < 32) sB2[tid] = b2[tid];
    if (tid < 7)  sBh[tid] = (tid < 3) ? bmc[tid] : (tid < 5 ? bco[tid - 3] : bip[tid - 5]);

    for (int i = tid; i < 32 * 64; i += 256) {
        int r = i >> 6, k = i & 63;
        float v = hbuf[(size_t)(r0 + r) * 64 + k];
        sH[r][k] = (v - mean[k]) * rstd[k] * gamma[k] + beta[k];
    }
    __syncthreads();

    for (int i = tid; i < 32 * 64; i += 256) {
        int r = i >> 6, o = i & 63;
        float a = sB1[o];
#pragma unroll
        for (int k = 0; k < 64; k++) a += sW1[o * 64 + k] * sH[r][k];
        sY1[r][o] = fmaxf(a, 0.f);
    }
    __syncthreads();

    for (int i = tid; i < 32 * 32; i += 256) {
        int r = i >> 5, o = i & 31;
        float a = sB2[o];
#pragma unroll
        for (int k = 0; k < 64; k++) a += sW2[o * 64 + k] * sY1[r][k];
        sY2[r][o] = fmaxf(a, 0.f);
    }
    __syncthreads();

    for (int i = tid; i < 32 * 7; i += 256) {
        int r = i / 7, o = i % 7;
        float a = sBh[o];
#pragma unroll
        for (int k = 0; k < 32; k++) a += sWh[o * 32 + k] * sY2[r][k];
        int row = r0 + r;
        if (o < 3)       out[(size_t)row * 3 + o] = a;
        else if (o < 5)  out[3072 + (size_t)row * 2 + (o - 3)] = a;
        else             out[5120 + (size_t)row * 2 + (o - 5)] = a;
    }
}

// ---------------------------------------------------------------------------
// Launch
// ---------------------------------------------------------------------------
extern "C" void kernel_launch(void* const* d_in, const int* in_sizes, int n_in,
                              void* d_out, int out_size)
{
    const float* x      = (const float*)d_in[0];
    const float* Wih0   = (const float*)d_in[1];
    const float* Whh0   = (const float*)d_in[2];
    const float* bih0   = (const float*)d_in[3];
    const float* bhh0   = (const float*)d_in[4];
    const float* Wih1   = (const float*)d_in[5];
    const float* Whh1   = (const float*)d_in[6];
    const float* bih1   = (const float*)d_in[7];
    const float* bhh1   = (const float*)d_in[8];
    const float* gamma  = (const float*)d_in[9];
    const float* beta   = (const float*)d_in[10];
    const float* W_fc1  = (const float*)d_in[11];
    const float* b_fc1  = (const float*)d_in[12];
    const float* W_fc2  = (const float*)d_in[13];
    const float* b_fc2  = (const float*)d_in[14];
    const float* W_mc   = (const float*)d_in[15];
    const float* b_mc   = (const float*)d_in[16];
    const float* W_co   = (const float*)d_in[17];
    const float* b_co   = (const float*)d_in[18];
    const float* W_ip   = (const float*)d_in[19];
    const float* b_ip   = (const float*)d_in[20];
    float* out = (float*)d_out;

    float* xw0;   cudaGetSymbolAddress((void**)&xw0,  g_xw0);
    float* hout;  cudaGetSymbolAddress((void**)&hout, g_hout);
    float* mean;  cudaGetSymbolAddress((void**)&mean, g_mean);
    float* rstd;  cudaGetSymbolAddress((void**)&rstd, g_rstd);

    // 1. input projection GEMM (f32x2)
    {
        dim3 grid((T_SZ * B_SZ) / 128, G4H / 64);
        input_gemm<<<grid, 256>>>(x, Wih0, bih0, bhh0, xw0);
    }

    // 2. fused 2-layer recurrence (f32x2, 4 rows/thread)
    {
        size_t smem = (size_t)LSTM_SMEM_FLOATS * sizeof(float);
        cudaFuncSetAttribute(lstm_fused, cudaFuncAttributeMaxDynamicSharedMemorySize, (int)smem);
        lstm_fused<<<B_SZ / RB, 128, smem>>>(xw0, Whh0, Wih1, Whh1, bih1, bhh1, hout);
    }

    // 3. batchnorm statistics
    bn_stats<<<H_SZ, 256>>>(hout, mean, rstd);

    // 4. BN apply + MLP + heads
    mlp_head<<<B_SZ / 32, 256>>>(hout, mean, rstd, gamma, beta,
                                 W_fc1, b_fc1, W_fc2, b_fc2,
                                 W_mc, b_mc, W_co, b_co, W_ip, b_ip, out);
}

// round 7
// speedup vs baseline: 1.8403x; 1.3619x over previous
#include <cuda_runtime.h>
#include <cuda_bf16.h>
#include <cstdint>

typedef unsigned long long u64;

#define B_SZ   1024
#define T_SZ   256
#define F_SZ   256
#define H_SZ   64
#define G4H    256
#define RB     8

// ---------------------------------------------------------------------------
// Scratch (device globals)
// ---------------------------------------------------------------------------
__device__ float g_xw0[(size_t)T_SZ * B_SZ * G4H];   // [T,B,4H]
__device__ float g_hout[(size_t)B_SZ * H_SZ];
__device__ float g_mean[H_SZ];
__device__ float g_rstd[H_SZ];

// ---------------------------------------------------------------------------
// helpers
// ---------------------------------------------------------------------------
__device__ __forceinline__ u64 ffma2(u64 a, u64 b, u64 c) {
    u64 d;
    asm("fma.rn.f32x2 %0, %1, %2, %3;" : "=l"(d) : "l"(a), "l"(b), "l"(c));
    return d;
}
__device__ __forceinline__ float hadd2(u64 a) {
    float lo, hi;
    asm("mov.b64 {%0, %1}, %2;" : "=f"(lo), "=f"(hi) : "l"(a));
    return lo + hi;
}
__device__ __forceinline__ float sigf(float x) {
    return __fdividef(1.f, 1.f + __expf(-x));
}
__device__ __forceinline__ float tanhfast(float x) {
    return 2.f * __fdividef(1.f, 1.f + __expf(-2.f * x)) - 1.f;
}

// bf16 hi/lo split: x = hi + lo with ~16 effective mantissa bits
__device__ __forceinline__ void cvt_hilo(float x, float y, uint32_t& hi, uint32_t& lo) {
    __nv_bfloat162 h = __floats2bfloat162_rn(x, y);
    float rx = x - __bfloat162float(h.x);
    float ry = y - __bfloat162float(h.y);
    __nv_bfloat162 l = __floats2bfloat162_rn(rx, ry);
    hi = *(uint32_t*)&h;
    lo = *(uint32_t*)&l;
}

// m16n8k16 row.col bf16 MMA, f32 accum
__device__ __forceinline__ void mma16816(float* c, const uint32_t* a, uint32_t b0, uint32_t b1) {
    asm volatile(
        "mma.sync.aligned.m16n8k16.row.col.f32.bf16.bf16.f32 "
        "{%0,%1,%2,%3}, {%4,%5,%6,%7}, {%8,%9}, {%0,%1,%2,%3};\n"
        : "+f"(c[0]), "+f"(c[1]), "+f"(c[2]), "+f"(c[3])
        : "r"(a[0]), "r"(a[1]), "r"(a[2]), "r"(a[3]), "r"(b0), "r"(b1));
}

// ---------------------------------------------------------------------------
// Kernel 1: input projection GEMM via bf16 tensor cores (hi/lo split = 3 MMAs)
//   xw0[m][n] = sum_k x_row(m)[k] * Wih0[n][k] + bias[n],  m = t*1024 + b
// One block: 128 m-rows, full K=256 in smem (pre-converted bf16x2 hi/lo),
// loop over 4 n-chunks of 64. 8 warps = 4(m) x 2(n); warp tile 32x32.
// ---------------------------------------------------------------------------
#define AS_STR 132              // u32 row stride (128 data + 4 pad -> conflict-free)
#define GEMM_SMEM_U32 (2*128*AS_STR + 2*64*AS_STR + 256)

__global__ __launch_bounds__(256) void input_gemm(
    const float* __restrict__ x,
    const float* __restrict__ Wih0,
    const float* __restrict__ bih0,
    const float* __restrict__ bhh0,
    float* __restrict__ xw0)
{
    extern __shared__ uint32_t smu[];
    uint32_t* As_hi = smu;                       // [128][132]
    uint32_t* As_lo = As_hi + 128 * AS_STR;
    uint32_t* Bs_hi = As_lo + 128 * AS_STR;      // [64][132]
    uint32_t* Bs_lo = Bs_hi + 64 * AS_STR;
    float*    sbias = (float*)(Bs_lo + 64 * AS_STR);   // [256]

    const int tid  = threadIdx.x;
    const int lane = tid & 31;
    const int wid  = tid >> 5;
    const int wm   = wid & 3;          // 4 warps along m
    const int wn   = wid >> 2;         // 2 warps along n
    const int g    = lane >> 2;
    const int t4   = lane & 3;
    const int m0   = blockIdx.x * 128;
    const int tt   = m0 >> 10;         // all 128 rows share t

    sbias[tid] = bih0[tid] + bhh0[tid];

    // ---- load + convert A: 128 rows x 256 k. 2 threads/row, 128 floats each.
    {
        int row = tid >> 1, half = tid & 1;
        int b   = (m0 + row) & 1023;
        const float4* src = (const float4*)(x + ((size_t)b * T_SZ + tt) * F_SZ + half * 128);
        uint32_t* dhi = As_hi + row * AS_STR + half * 64;
        uint32_t* dlo = As_lo + row * AS_STR + half * 64;
#pragma unroll 8
        for (int q = 0; q < 32; q++) {
            float4 v = src[q];
            cvt_hilo(v.x, v.y, dhi[2 * q],     dlo[2 * q]);
            cvt_hilo(v.z, v.w, dhi[2 * q + 1], dlo[2 * q + 1]);
        }
    }

    for (int nc = 0; nc < 4; nc++) {
        const int n0 = nc * 64;
        // ---- load + convert B chunk: 64 rows x 256 k. 4 threads/row.
        {
            int row = tid >> 2, q4 = tid & 3;
            const float4* src = (const float4*)(Wih0 + (size_t)(n0 + row) * F_SZ + q4 * 64);
            uint32_t* dhi = Bs_hi + row * AS_STR + q4 * 32;
            uint32_t* dlo = Bs_lo + row * AS_STR + q4 * 32;
#pragma unroll 8
            for (int q = 0; q < 16; q++) {
                float4 v = src[q];
                cvt_hilo(v.x, v.y, dhi[2 * q],     dlo[2 * q]);
                cvt_hilo(v.z, v.w, dhi[2 * q + 1], dlo[2 * q + 1]);
            }
        }
        __syncthreads();

        float acc[2][4][4];
#pragma unroll
        for (int mi = 0; mi < 2; mi++)
#pragma unroll
            for (int ni = 0; ni < 4; ni++)
#pragma unroll
                for (int q = 0; q < 4; q++) acc[mi][ni][q] = 0.f;

#pragma unroll 4
        for (int ks = 0; ks < 16; ks++) {
            uint32_t ah[2][4], al[2][4];
#pragma unroll
            for (int mi = 0; mi < 2; mi++) {
                const uint32_t* ph = As_hi + (wm * 32 + mi * 16 + g) * AS_STR + ks * 8 + t4;
                const uint32_t* pl = As_lo + (wm * 32 + mi * 16 + g) * AS_STR + ks * 8 + t4;
                ah[mi][0] = ph[0];            ah[mi][2] = ph[4];
                ah[mi][1] = ph[8 * AS_STR];   ah[mi][3] = ph[8 * AS_STR + 4];
                al[mi][0] = pl[0];            al[mi][2] = pl[4];
                al[mi][1] = pl[8 * AS_STR];   al[mi][3] = pl[8 * AS_STR + 4];
            }
#pragma unroll
            for (int ni = 0; ni < 4; ni++) {
                int n = wn * 32 + ni * 8 + g;
                uint32_t bh0 = Bs_hi[n * AS_STR + ks * 8 + t4];
                uint32_t bh1 = Bs_hi[n * AS_STR + ks * 8 + t4 + 4];
                uint32_t bl0 = Bs_lo[n * AS_STR + ks * 8 + t4];
                uint32_t bl1 = Bs_lo[n * AS_STR + ks * 8 + t4 + 4];
#pragma unroll
                for (int mi = 0; mi < 2; mi++) {
                    mma16816(acc[mi][ni], ah[mi], bh0, bh1);   // hi*hi
                    mma16816(acc[mi][ni], al[mi], bh0, bh1);   // lo*hi
                    mma16816(acc[mi][ni], ah[mi], bl0, bl1);   // hi*lo
                }
            }
        }

        // ---- store with bias
#pragma unroll
        for (int mi = 0; mi < 2; mi++) {
#pragma unroll
            for (int ni = 0; ni < 4; ni++) {
                int r  = wm * 32 + mi * 16 + g;
                int cl = n0 + wn * 32 + ni * 8 + 2 * t4;
                size_t m = (size_t)(m0 + r);
                xw0[m * G4H + cl]           = acc[mi][ni][0] + sbias[cl];
                xw0[m * G4H + cl + 1]       = acc[mi][ni][1] + sbias[cl + 1];
                xw0[(m + 8) * G4H + cl]     = acc[mi][ni][2] + sbias[cl];
                xw0[(m + 8) * G4H + cl + 1] = acc[mi][ni][3] + sbias[cl + 1];
            }
        }
        __syncthreads();   // protect Bs before next chunk overwrite
    }
}

// ---------------------------------------------------------------------------
// Kernel 2: fused 2-layer LSTM recurrence (R4-validated: 128 thr, 4 rows/thr)
// ---------------------------------------------------------------------------
#define LSTM_SMEM_FLOATS (3*16384 + 2*512 + 2*512)

__global__ __launch_bounds__(128) void lstm_fused(
    const float* __restrict__ xw0,
    const float* __restrict__ Whh0,
    const float* __restrict__ Wih1,
    const float* __restrict__ Whh1,
    const float* __restrict__ bih1,
    const float* __restrict__ bhh1,
    float* __restrict__ hout)
{
    extern __shared__ float sm[];
    float* sw0   = sm;                 // 16384
    float* sw1   = sm + 16384;
    float* sw2   = sm + 32768;
    float* h0buf = sm + 49152;         // [2][512]
    float* h1buf = sm + 49152 + 1024;  // [2][512]

    const int tid   = threadIdx.x;
    const int k     = tid & 63;
    const int grp   = tid >> 6;
    const int rbase = grp * 4;
    const int b0    = blockIdx.x * RB;

    for (int i = tid; i < 16384; i += 128) {
        int g = i >> 6, j = i & 63;
        int d = ((j >> 1) * 256 + g) * 2 + (j & 1);
        sw0[d] = Whh0[i];
        sw1[d] = Wih1[i];
        sw2[d] = Whh1[i];
    }
    for (int i = tid; i < 1024; i += 128) { h0buf[i] = 0.f; h1buf[i] = 0.f; }

    float bz[4];
#pragma unroll
    for (int gi = 0; gi < 4; gi++) bz[gi] = bih1[gi * 64 + k] + bhh1[gi * 64 + k];

    const float* xp[4];
#pragma unroll
    for (int rr = 0; rr < 4; rr++)
        xp[rr] = xw0 + (size_t)(b0 + rbase + rr) * G4H + k;

    float xv[4][4];
#pragma unroll
    for (int gi = 0; gi < 4; gi++)
#pragma unroll
        for (int rr = 0; rr < 4; rr++) xv[gi][rr] = xp[rr][gi * 64];

    float c0[4] = {0.f, 0.f, 0.f, 0.f};
    float c1[4] = {0.f, 0.f, 0.f, 0.f};
    float h1v[4] = {0.f, 0.f, 0.f, 0.f};

    __syncthreads();

    for (int t = 0; t < T_SZ; t++) {
        const float* h0r = h0buf + (t & 1) * 512;
        float*       h0w = h0buf + ((t + 1) & 1) * 512;
        const float* h1r = h1buf + (t & 1) * 512;
        float*       h1w = h1buf + ((t + 1) & 1) * 512;

        u64 acc[4][4];
#pragma unroll
        for (int gi = 0; gi < 4; gi++)
#pragma unroll
            for (int rr = 0; rr < 4; rr++) acc[gi][rr] = 0ull;

#pragma unroll 8
        for (int jj = 0; jj < 32; jj++) {
            const float* wrow = sw0 + jj * 512 + k * 2;
            u64 w[4];
            w[0] = *(const u64*)(wrow);
            w[1] = *(const u64*)(wrow + 128);
            w[2] = *(const u64*)(wrow + 256);
            w[3] = *(const u64*)(wrow + 384);
            u64 hv[4];
#pragma unroll
            for (int rr = 0; rr < 4; rr++)
                hv[rr] = *(const u64*)(h0r + (rbase + rr) * 64 + jj * 2);
#pragma unroll
            for (int gi = 0; gi < 4; gi++)
#pragma unroll
                for (int rr = 0; rr < 4; rr++)
                    acc[gi][rr] = ffma2(w[gi], hv[rr], acc[gi][rr]);
        }

#pragma unroll
        for (int rr = 0; rr < 4; rr++) {
            float zi = hadd2(acc[0][rr]) + xv[0][rr];
            float zf = hadd2(acc[1][rr]) + xv[1][rr];
            float zg = hadd2(acc[2][rr]) + xv[2][rr];
            float zo = hadd2(acc[3][rr]) + xv[3][rr];
            c0[rr] = sigf(zf) * c0[rr] + sigf(zi) * tanhfast(zg);
            h0w[(rbase + rr) * 64 + k] = sigf(zo) * tanhfast(c0[rr]);
        }

        if (t < T_SZ - 1) {
            size_t off = (size_t)(t + 1) * ((size_t)B_SZ * G4H);
#pragma unroll
            for (int gi = 0; gi < 4; gi++)
#pragma unroll
                for (int rr = 0; rr < 4; rr++)
                    xv[gi][rr] = xp[rr][off + gi * 64];
        }
        __syncthreads();

#pragma unroll
        for (int gi = 0; gi < 4; gi++)
#pragma unroll
            for (int rr = 0; rr < 4; rr++) acc[gi][rr] = 0ull;

#pragma unroll 4
        for (int jj = 0; jj < 32; jj++) {
            const float* arow = sw1 + jj * 512 + k * 2;
            const float* brow = sw2 + jj * 512 + k * 2;
            u64 wa[4], wb[4];
            wa[0] = *(const u64*)(arow);
            wa[1] = *(const u64*)(arow + 128);
            wa[2] = *(const u64*)(arow + 256);
            wa[3] = *(const u64*)(arow + 384);
            wb[0] = *(const u64*)(brow);
            wb[1] = *(const u64*)(brow + 128);
            wb[2] = *(const u64*)(brow + 256);
            wb[3] = *(const u64*)(brow + 384);
            u64 h0v[4], h1vv[4];
#pragma unroll
            for (int rr = 0; rr < 4; rr++) {
                h0v[rr]  = *(const u64*)(h0w + (rbase + rr) * 64 + jj * 2);
                h1vv[rr] = *(const u64*)(h1r + (rbase + rr) * 64 + jj * 2);
            }
#pragma unroll
            for (int gi = 0; gi < 4; gi++)
#pragma unroll
                for (int rr = 0; rr < 4; rr++) {
                    acc[gi][rr] = ffma2(wa[gi], h0v[rr], acc[gi][rr]);
                    acc[gi][rr] = ffma2(wb[gi], h1vv[rr], acc[gi][rr]);
                }
        }

#pragma unroll
        for (int rr = 0; rr < 4; rr++) {
            float zi = hadd2(acc[0][rr]) + bz[0];
            float zf = hadd2(acc[1][rr]) + bz[1];
            float zg = hadd2(acc[2][rr]) + bz[2];
            float zo = hadd2(acc[3][rr]) + bz[3];
            c1[rr] = sigf(zf) * c1[rr] + sigf(zi) * tanhfast(zg);
            h1v[rr] = sigf(zo) * tanhfast(c1[rr]);
            h1w[(rbase + rr) * 64 + k] = h1v[rr];
        }
        __syncthreads();
    }

#pragma unroll
    for (int rr = 0; rr < 4; rr++)
        hout[(size_t)(b0 + rbase + rr) * H_SZ + k] = h1v[rr];
}

// ---------------------------------------------------------------------------
// Kernel 3: batchnorm statistics
// ---------------------------------------------------------------------------
__global__ __launch_bounds__(256) void bn_stats(
    const float* __restrict__ h, float* __restrict__ mean, float* __restrict__ rstd)
{
    const int k = blockIdx.x;
    __shared__ float s1[256], s2[256];
    float a = 0.f, b = 0.f;
    for (int i = threadIdx.x; i < B_SZ; i += 256) {
        float v = h[(size_t)i * H_SZ + k];
        a += v; b += v * v;
    }
    s1[threadIdx.x] = a; s2[threadIdx.x] = b;
    __syncthreads();
    for (int s = 128; s > 0; s >>= 1) {
        if (threadIdx.x < s) { s1[threadIdx.x] += s1[threadIdx.x + s]; s2[threadIdx.x] += s2[threadIdx.x + s]; }
        __syncthreads();
    }
    if (threadIdx.x == 0) {
        float m = s1[0] / (float)B_SZ;
        float var = s2[0] / (float)B_SZ - m * m;
        mean[k] = m;
        rstd[k] = rsqrtf(var + 1e-5f);
    }
}

// ---------------------------------------------------------------------------
// Kernel 4: BN apply + MLP trunk + 3 heads
// ---------------------------------------------------------------------------
__global__ __launch_bounds__(256) void mlp_head(
    const float* __restrict__ hbuf,
    const float* __restrict__ mean, const float* __restrict__ rstd,
    const float* __restrict__ gamma, const float* __restrict__ beta,
    const float* __restrict__ W1, const float* __restrict__ b1,
    const float* __restrict__ W2, const float* __restrict__ b2,
    const float* __restrict__ Wmc, const float* __restrict__ bmc,
    const float* __restrict__ Wco, const float* __restrict__ bco,
    const float* __restrict__ Wip, const float* __restrict__ bip,
    float* __restrict__ out)
{
    __shared__ float sH[32][64];
    __shared__ float sY1[32][64];
    __shared__ float sY2[32][32];
    __shared__ float sW1[64 * 64];
    __shared__ float sW2[32 * 64];
    __shared__ float sWh[7 * 32];
    __shared__ float sB1[64], sB2[32], sBh[7];

    const int tid = threadIdx.x;
    const int r0  = blockIdx.x * 32;

    for (int i = tid; i < 64 * 64; i += 256) sW1[i] = W1[i];
    for (int i = tid; i < 32 * 64; i += 256) sW2[i] = W2[i];
    for (int i = tid; i < 7 * 32; i += 256)
        sWh[i] = (i < 96) ? Wmc[i] : (i < 160 ? Wco[i - 96] : Wip[i - 160]);
    if (tid < 64) sB1[tid] = b1[tid];
    if (tid < 32) sB2[tid] = b2[tid];
    if (tid < 7)  sBh[tid] = (tid < 3) ? bmc[tid] : (tid < 5 ? bco[tid - 3] : bip[tid - 5]);

    for (int i = tid; i < 32 * 64; i += 256) {
        int r = i >> 6, k = i & 63;
        float v = hbuf[(size_t)(r0 + r) * 64 + k];
        sH[r][k] = (v - mean[k]) * rstd[k] * gamma[k] + beta[k];
    }
    __syncthreads();

    for (int i = tid; i < 32 * 64; i += 256) {
        int r = i >> 6, o = i & 63;
        float a = sB1[o];
#pragma unroll
        for (int k = 0; k < 64; k++) a += sW1[o * 64 + k] * sH[r][k];
        sY1[r][o] = fmaxf(a, 0.f);
    }
    __syncthreads();

    for (int i = tid; i < 32 * 32; i += 256) {
        int r = i >> 5, o = i & 31;
        float a = sB2[o];
#pragma unroll
        for (int k = 0; k < 64; k++) a += sW2[o * 64 + k] * sY1[r][k];
        sY2[r][o] = fmaxf(a, 0.f);
    }
    __syncthreads();

    for (int i = tid; i < 32 * 7; i += 256) {
        int r = i / 7, o = i % 7;
        float a = sBh[o];
#pragma unroll
        for (int k = 0; k < 32; k++) a += sWh[o * 32 + k] * sY2[r][k];
        int row = r0 + r;
        if (o < 3)       out[(size_t)row * 3 + o] = a;
        else if (o < 5)  out[3072 + (size_t)row * 2 + (o - 3)] = a;
        else             out[5120 + (size_t)row * 2 + (o - 5)] = a;
    }
}

// ---------------------------------------------------------------------------
// Launch
// ---------------------------------------------------------------------------
extern "C" void kernel_launch(void* const* d_in, const int* in_sizes, int n_in,
                              void* d_out, int out_size)
{
    const float* x      = (const float*)d_in[0];
    const float* Wih0   = (const float*)d_in[1];
    const float* Whh0   = (const float*)d_in[2];
    const float* bih0   = (const float*)d_in[3];
    const float* bhh0   = (const float*)d_in[4];
    const float* Wih1   = (const float*)d_in[5];
    const float* Whh1   = (const float*)d_in[6];
    const float* bih1   = (const float*)d_in[7];
    const float* bhh1   = (const float*)d_in[8];
    const float* gamma  = (const float*)d_in[9];
    const float* beta   = (const float*)d_in[10];
    const float* W_fc1  = (const float*)d_in[11];
    const float* b_fc1  = (const float*)d_in[12];
    const float* W_fc2  = (const float*)d_in[13];
    const float* b_fc2  = (const float*)d_in[14];
    const float* W_mc   = (const float*)d_in[15];
    const float* b_mc   = (const float*)d_in[16];
    const float* W_co   = (const float*)d_in[17];
    const float* b_co   = (const float*)d_in[18];
    const float* W_ip   = (const float*)d_in[19];
    const float* b_ip   = (const float*)d_in[20];
    float* out = (float*)d_out;

    float* xw0;   cudaGetSymbolAddress((void**)&xw0,  g_xw0);
    float* hout;  cudaGetSymbolAddress((void**)&hout, g_hout);
    float* mean;  cudaGetSymbolAddress((void**)&mean, g_mean);
    float* rstd;  cudaGetSymbolAddress((void**)&rstd, g_rstd);

    // 1. input projection GEMM (bf16 tensor cores, hi/lo split)
    {
        size_t smem = (size_t)GEMM_SMEM_U32 * sizeof(uint32_t);
        cudaFuncSetAttribute(input_gemm, cudaFuncAttributeMaxDynamicSharedMemorySize, (int)smem);
        input_gemm<<<(T_SZ * B_SZ) / 128, 256, smem>>>(x, Wih0, bih0, bhh0, xw0);
    }

    // 2. fused 2-layer recurrence
    {
        size_t smem = (size_t)LSTM_SMEM_FLOATS * sizeof(float);
        cudaFuncSetAttribute(lstm_fused, cudaFuncAttributeMaxDynamicSharedMemorySize, (int)smem);
        lstm_fused<<<B_SZ / RB, 128, smem>>>(xw0, Whh0, Wih1, Whh1, bih1, bhh1, hout);
    }

    // 3. batchnorm statistics
    bn_stats<<<H_SZ, 256>>>(hout, mean, rstd);

    // 4. BN apply + MLP + heads
    mlp_head<<<B_SZ / 32, 256>>>(hout, mean, rstd, gamma, beta,
                                 W_fc1, b_fc1, W_fc2, b_fc2,
                                 W_mc, b_mc, W_co, b_co, W_ip, b_ip, out);
}